// round 9
// baseline (speedup 1.0000x reference)
#include <cuda_runtime.h>
#include <cstdint>

#define NB 4096
#define NR 64
#define ND 512
#define D2 256              // ND/2
#define BPC 32              // b-rows per CTA
#define GRID (NB / BPC)     // 128
#define NT 512

typedef unsigned long long u64;

__device__ __forceinline__ void fma2(u64 &d, u64 a, u64 b) {
    asm("fma.rn.f32x2 %0, %1, %2, %0;" : "+l"(d) : "l"(a), "l"(b));
}
__device__ __forceinline__ float hsum2(u64 a) {
    float x, y;
    asm("mov.b64 {%0, %1}, %2;" : "=f"(x), "=f"(y) : "l"(a));
    return x + y;
}

__device__ float g_part[GRID];
__device__ int   g_ctr = 0;

// ---- dynamic smem layout (bytes) ----
#define OFF_E   0
#define SZ_E    (D2 * 512)              // [d2][r] float2 rows (512B)      = 131072
#define OFF_W   (OFF_E + SZ_E)          // [d2][b] float2 rows (256B)      = 65536
#define SZ_W    (D2 * 256)              //   REUSED post-mainloop as partials:
                                        //   [4 slices][32 b][64 r] float  = 32768
#define OFF_EN  (OFF_W + SZ_W)          // 64 f
#define OFF_WN  (OFF_EN + 256)          // 32 f
#define OFF_Y   (OFF_WN + 128)          // 32 i
#define OFF_LS  (OFF_Y + 128)           // 32 f
#define OFF_PE  (OFF_LS + 128)          // 512 f
#define OFF_PW  (OFF_PE + 2048)         // 512 f
#define SMEM_TOTAL (OFF_PW + 2048)      // 201344 B

__global__ __launch_bounds__(NT, 1)
void k_fused(const float* __restrict__ W, const float* __restrict__ E,
             const float* __restrict__ Lb, float* __restrict__ pred,
             float* __restrict__ lossp) {
    extern __shared__ char sm[];
    float* sE    = (float*)(sm + OFF_E);
    char*  sW    = sm + OFF_W;
    float* sPart = (float*)(sm + OFF_W);   // alias, valid post-mainloop
    float* sEn = (float*)(sm + OFF_EN);
    float* sWn = (float*)(sm + OFF_WN);
    int*   sY  = (int*)(sm + OFF_Y);
    float* sLs = (float*)(sm + OFF_LS);
    float* sPE = (float*)(sm + OFF_PE);
    float* sPW = (float*)(sm + OFF_PW);
    __shared__ int sFlag;

    const int t  = threadIdx.x;
    const int L  = t & 31;
    const int wi = t >> 5;
    const int b0 = blockIdx.x * BPC;

    // ---------- stage E: gmem [r][d] -> smem [d2][r] float2; fused |e|^2 ----------
    {
        const int r = t & 63, g = t >> 6;          // g in 0..7
        const float4* Er = (const float4*)(E + (size_t)r * ND);
        float enp = 0.f;
        #pragma unroll 4
        for (int k = 0; k < 16; ++k) {
            int c = g + (k << 3);
            float4 v = Er[c];
            enp = fmaf(v.x, v.x, enp); enp = fmaf(v.y, v.y, enp);
            enp = fmaf(v.z, v.z, enp); enp = fmaf(v.w, v.w, enp);
            *(float2*)((char*)sE + (size_t)(2 * c)     * 512 + r * 8) = make_float2(v.x, v.y);
            *(float2*)((char*)sE + (size_t)(2 * c + 1) * 512 + r * 8) = make_float2(v.z, v.w);
        }
        sPE[t] = enp;
    }
    // ---------- stage W: gmem [b][d] -> smem [d2][b] float2; fused |w|^2 ----------
    {
        const int b = t & 31, g = t >> 5;          // g in 0..15
        const float4* Wb = (const float4*)(W + (size_t)(b0 + b) * ND);
        float wnp = 0.f;
        #pragma unroll 4
        for (int k = 0; k < 8; ++k) {
            int c = g + (k << 4);
            float4 v = Wb[c];
            wnp = fmaf(v.x, v.x, wnp); wnp = fmaf(v.y, v.y, wnp);
            wnp = fmaf(v.z, v.z, wnp); wnp = fmaf(v.w, v.w, wnp);
            *(float2*)(sW + (size_t)(2 * c)     * 256 + b * 8) = make_float2(v.x, v.y);
            *(float2*)(sW + (size_t)(2 * c + 1) * 256 + b * 8) = make_float2(v.z, v.w);
        }
        sPW[t] = wnp;
    }
    // ---------- label argmax: warp wi handles rows 2wi, 2wi+1 ----------
    {
        #pragma unroll
        for (int j = 0; j < 2; ++j) {
            int bl = wi * 2 + j;
            const float* Lr = Lb + (size_t)(b0 + bl) * NR;
            float lv = Lr[L]; int li = L;
            float l2 = Lr[L + 32];
            if (l2 > lv) { lv = l2; li = L + 32; }   // strict > keeps lower index on ties
            #pragma unroll
            for (int o = 16; o; o >>= 1) {
                float ov = __shfl_xor_sync(0xffffffffu, lv, o);
                int   oi = __shfl_xor_sync(0xffffffffu, li, o);
                if (ov > lv || (ov == lv && oi < li)) { lv = ov; li = oi; }
            }
            if (L == 0) sY[bl] = li;
        }
    }
    __syncthreads();

    // ---------- norm combines ----------
    if (t < 64) {
        float s = 0.f;
        #pragma unroll
        for (int k = 0; k < 8; ++k) s += sPE[t + 64 * k];
        sEn[t] = s;
    } else if (t < 96) {
        int u = t - 64; float s = 0.f;
        #pragma unroll
        for (int k = 0; k < 16; ++k) s += sPW[u + 32 * k];
        sWn[u] = s;
    }

    // ================= mainloop: 16 warps = 4 b-groups x 4 k-slices =================
    // lane tile: 4 r (r = 4*rq .. 4*rq+3) x 4 b (b = 8*wG + 4*bh .. +3), d-parity packed
    const int s  = wi >> 2;       // k-slice: d2 in [64s, 64(s+1))
    const int wG = wi & 3;        // b-group of 8
    const int rq = L & 15;        // r-quad
    const int bh = L >> 4;        // b-half within group
    u64 acc[4][4] = {};           // [b'][r'] f32x2 over d-parity

    {
        const char* eb = (const char*)sE + (size_t)(s * 64) * 512 + rq * 32;
        const char* wb = sW + (size_t)(s * 64) * 256 + (wG * 8 + bh * 4) * 8;
        ulonglong2 e0 = *(const ulonglong2*)eb;          // {r0:(d,d+1)},{r1:(d,d+1)}
        ulonglong2 e1 = *(const ulonglong2*)(eb + 16);   // r2, r3
        ulonglong2 w0 = *(const ulonglong2*)wb;          // b0, b1
        ulonglong2 w1 = *(const ulonglong2*)(wb + 16);   // b2, b3
        #pragma unroll 4
        for (int j = 0; j < 64; ++j) {
            // prefetch next d2 (final iter over-reads in-bounds smem; unused)
            eb += 512; wb += 256;
            ulonglong2 ne0 = *(const ulonglong2*)eb;
            ulonglong2 ne1 = *(const ulonglong2*)(eb + 16);
            ulonglong2 nw0 = *(const ulonglong2*)wb;
            ulonglong2 nw1 = *(const ulonglong2*)(wb + 16);

            fma2(acc[0][0], w0.x, e0.x); fma2(acc[0][1], w0.x, e0.y);
            fma2(acc[0][2], w0.x, e1.x); fma2(acc[0][3], w0.x, e1.y);
            fma2(acc[1][0], w0.y, e0.x); fma2(acc[1][1], w0.y, e0.y);
            fma2(acc[1][2], w0.y, e1.x); fma2(acc[1][3], w0.y, e1.y);
            fma2(acc[2][0], w1.x, e0.x); fma2(acc[2][1], w1.x, e0.y);
            fma2(acc[2][2], w1.x, e1.x); fma2(acc[2][3], w1.x, e1.y);
            fma2(acc[3][0], w1.y, e0.x); fma2(acc[3][1], w1.y, e0.y);
            fma2(acc[3][2], w1.y, e1.x); fma2(acc[3][3], w1.y, e1.y);

            e0 = ne0; e1 = ne1; w0 = nw0; w1 = nw1;
        }
    }
    __syncthreads();   // all warps done reading sW -> safe to overwrite with partials

    // ---------- dump partial dots: [slice][b][r] float, packed float4 over r ----------
    #pragma unroll
    for (int bp = 0; bp < 4; ++bp) {
        const int bl = wG * 8 + bh * 4 + bp;
        float4 d4 = make_float4(hsum2(acc[bp][0]), hsum2(acc[bp][1]),
                                hsum2(acc[bp][2]), hsum2(acc[bp][3]));
        *(float4*)(sPart + ((size_t)(s * 32 + bl) * 64 + rq * 4)) = d4;
    }
    __syncthreads();

    // ================= epilogue: 16 warps x 2 b each =================
    {
        const int p = wi >> 2;                     // pair index 0..3
        float2 en2 = *(const float2*)(sEn + 2 * L);
        #pragma unroll
        for (int jj = 0; jj < 2; ++jj) {
            const int bl = (wi & 3) * 8 + p * 2 + jj;
            float dot0 = 0.f, dot1 = 0.f;
            #pragma unroll
            for (int k = 0; k < 4; ++k) {
                float2 q = *(const float2*)(sPart + ((size_t)(k * 32 + bl) * 64 + 2 * L));
                dot0 += q.x; dot1 += q.y;
            }
            float wn = sWn[bl];
            int   y  = sY[bl];
            float da = fmaf(-2.f, dot0, wn + en2.x);     // dist^2(b, 2L)
            float db = fmaf(-2.f, dot1, wn + en2.y);     // dist^2(b, 2L+1)
            float v1, v2; int i1;
            if (db > da) { v1 = db; i1 = 2 * L + 1; v2 = da; }
            else         { v1 = da; i1 = 2 * L;     v2 = db; }
            float pys = (y & 1) ? db : da;
            #pragma unroll
            for (int o = 16; o; o >>= 1) {
                float ov1 = __shfl_xor_sync(0xffffffffu, v1, o);
                int   oi1 = __shfl_xor_sync(0xffffffffu, i1, o);
                float ov2 = __shfl_xor_sync(0xffffffffu, v2, o);
                if (ov1 > v1 || (ov1 == v1 && oi1 < i1)) {
                    v2 = fmaxf(v1, ov2); v1 = ov1; i1 = oi1;
                } else {
                    v2 = fmaxf(v2, ov1);
                }
            }
            float plus  = __shfl_sync(0xffffffffu, pys, y >> 1);
            float minus = (i1 == y) ? v2 : v1;
            if (L == 0)
                sLs[bl] = 1.0f + sqrtf(fmaxf(plus, 0.f)) - sqrtf(fmaxf(minus, 0.f));
            float2 pr = make_float2((2 * L == i1) ? 1.f : 0.f,
                                    (2 * L + 1 == i1) ? 1.f : 0.f);
            *(float2*)(pred + (size_t)(b0 + bl) * NR + 2 * L) = pr;
        }
    }
    __syncthreads();

    // ================= per-CTA loss partial + deterministic last-CTA mean =================
    if (t < 32) {
        float sv = sLs[t];
        #pragma unroll
        for (int o = 16; o; o >>= 1) sv += __shfl_xor_sync(0xffffffffu, sv, o);
        if (t == 0) {
            g_part[blockIdx.x] = sv;
            __threadfence();
            int old = atomicAdd(&g_ctr, 1);
            sFlag = (old == GRID - 1) ? 1 : 0;
        }
    }
    __syncthreads();
    if (sFlag && t < 32) {
        float sv = 0.f;
        #pragma unroll
        for (int k = 0; k < GRID / 32; ++k) {
            float v;
            asm("ld.global.cg.f32 %0, [%1];" : "=f"(v) : "l"(g_part + t + 32 * k));
            sv += v;
        }
        #pragma unroll
        for (int o = 16; o; o >>= 1) sv += __shfl_xor_sync(0xffffffffu, sv, o);
        if (t == 0) { *lossp = sv * (1.0f / (float)NB); g_ctr = 0; }
    }
}

extern "C" void kernel_launch(void* const* d_in, const int* in_sizes, int n_in,
                              void* d_out, int out_size) {
    const float* W = nullptr; const float* E = nullptr; const float* L = nullptr;
    for (int i = 0; i < n_in; ++i) {
        if      (in_sizes[i] == NB * ND) W = (const float*)d_in[i];
        else if (in_sizes[i] == NR * ND) E = (const float*)d_in[i];
        else if (in_sizes[i] == NB * NR) L = (const float*)d_in[i];
    }
    float* out = (float*)d_out;
    cudaFuncSetAttribute(k_fused, cudaFuncAttributeMaxDynamicSharedMemorySize, SMEM_TOTAL);
    k_fused<<<GRID, NT, SMEM_TOTAL>>>(W, E, L, out, out + (out_size - 1));
}

// round 15
// speedup vs baseline: 1.3750x; 1.3750x over previous
#include <cuda_runtime.h>
#include <cstdint>

#define NB 4096
#define NR 64
#define ND 512
#define MTILE 32
#define GRID (NB / MTILE)    // 128
#define NT 256

typedef unsigned int u32;

__device__ float g_part[GRID];
__device__ int   g_ctr = 0;

// ---- smem layout (bytes); bf16 tiles use 1040B row pitch (520 bf16) ----
#define PITCH   1040
#define OFF_WH  0
#define OFF_WL  (OFF_WH + 32 * PITCH)     // 33280
#define OFF_EH  (OFF_WL + 32 * PITCH)     // 66560
#define OFF_EL  (OFF_EH + 64 * PITCH)     // 133120
#define OFF_WN2 (OFF_EL + 64 * PITCH)     // 199680  (256 f)
#define OFF_EN2 (OFF_WN2 + 1024)          // 200704  (256 f)
#define OFF_EN  (OFF_EN2 + 1024)          // 201728  (64 f)
#define OFF_WN  (OFF_EN + 256)            // 201984  (32 f)
#define OFF_LS  (OFF_WN + 128)            // 202112  (32 f)
#define SMEM_TOTAL (OFF_LS + 128)         // 202240
#define OFF_D   OFF_WH                    // dots [32][DPITCH] f, reuses W region
#define DPITCH  68

__device__ __forceinline__ u32 smem_u32(const void* p) {
    u32 a; asm("{ .reg .u64 t; cvta.to.shared.u64 t, %1; cvt.u32.u64 %0, t; }" : "=r"(a) : "l"(p));
    return a;
}
__device__ __forceinline__ u32 pk(float lo, float hi) {   // -> bf16x2 {hi|lo}
    u32 r; asm("cvt.rn.bf16x2.f32 %0, %1, %2;" : "=r"(r) : "f"(hi), "f"(lo)); return r;
}
// 8 fp32 -> bf16 hi uint4 + residual-lo uint4
__device__ __forceinline__ void cvt8(float4 a, float4 b, uint4 &H, uint4 &Lo) {
    H.x = pk(a.x, a.y); H.y = pk(a.z, a.w); H.z = pk(b.x, b.y); H.w = pk(b.z, b.w);
    float l0 = a.x - __uint_as_float(H.x << 16);
    float l1 = a.y - __uint_as_float(H.x & 0xffff0000u);
    float l2 = a.z - __uint_as_float(H.y << 16);
    float l3 = a.w - __uint_as_float(H.y & 0xffff0000u);
    float l4 = b.x - __uint_as_float(H.z << 16);
    float l5 = b.y - __uint_as_float(H.z & 0xffff0000u);
    float l6 = b.z - __uint_as_float(H.w << 16);
    float l7 = b.w - __uint_as_float(H.w & 0xffff0000u);
    Lo.x = pk(l0, l1); Lo.y = pk(l2, l3); Lo.z = pk(l4, l5); Lo.w = pk(l6, l7);
}
#define LDM4(r0, r1, r2, r3, a) \
    asm volatile("ldmatrix.sync.aligned.m8n8.x4.shared.b16 {%0,%1,%2,%3}, [%4];" \
        : "=r"(r0), "=r"(r1), "=r"(r2), "=r"(r3) : "r"(a))
#define MMA(c, a0, a1, a2, a3, b0, b1) \
    asm volatile("mma.sync.aligned.m16n8k16.row.col.f32.bf16.bf16.f32 " \
        "{%0,%1,%2,%3}, {%4,%5,%6,%7}, {%8,%9}, {%0,%1,%2,%3};" \
        : "+f"((c)[0]), "+f"((c)[1]), "+f"((c)[2]), "+f"((c)[3]) \
        : "r"(a0), "r"(a1), "r"(a2), "r"(a3), "r"(b0), "r"(b1))

__global__ __launch_bounds__(NT, 1)
void k_fused(const float* __restrict__ W, const float* __restrict__ E,
             const float* __restrict__ Lb, float* __restrict__ pred,
             float* __restrict__ lossp) {
    extern __shared__ char sm[];
    const u32 smb = smem_u32(sm);
    float* sWn2 = (float*)(sm + OFF_WN2);
    float* sEn2 = (float*)(sm + OFF_EN2);
    float* sEn  = (float*)(sm + OFF_EN);
    float* sWn  = (float*)(sm + OFF_WN);
    float* sLs  = (float*)(sm + OFF_LS);
    float* sD   = (float*)(sm + OFF_D);
    __shared__ int sFlag;

    const int t  = threadIdx.x;
    const int L  = t & 31;
    const int wi = t >> 5;
    const int b0 = blockIdx.x * MTILE;

    // ---- stage W: 32 rows bf16 hi/lo; lane=row => conflict-free STS; fused |w|^2 ----
    {
        const int r = t & 31, o = t >> 5;             // o in 0..7, 64 cols each
        const float4* Wb4 = (const float4*)(W + (size_t)(b0 + r) * ND);
        float wnp = 0.f;
        #pragma unroll
        for (int j = 0; j < 8; ++j) {
            float4 a = Wb4[o * 16 + 2 * j], b = Wb4[o * 16 + 2 * j + 1];
            wnp = fmaf(a.x, a.x, wnp); wnp = fmaf(a.y, a.y, wnp);
            wnp = fmaf(a.z, a.z, wnp); wnp = fmaf(a.w, a.w, wnp);
            wnp = fmaf(b.x, b.x, wnp); wnp = fmaf(b.y, b.y, wnp);
            wnp = fmaf(b.z, b.z, wnp); wnp = fmaf(b.w, b.w, wnp);
            uint4 H, Lo; cvt8(a, b, H, Lo);
            const int off = r * PITCH + o * 128 + j * 16;
            *(uint4*)(sm + OFF_WH + off) = H;
            *(uint4*)(sm + OFF_WL + off) = Lo;
        }
        sWn2[t] = wnp;
    }
    // ---- stage E: 64 rows bf16 hi/lo; fused |e|^2 ----
    {
        const int r = t & 63, q = t >> 6;             // q in 0..3, 128 cols each
        const float4* Er4 = (const float4*)(E + (size_t)r * ND);
        float enp = 0.f;
        #pragma unroll
        for (int j = 0; j < 16; ++j) {
            float4 a = Er4[q * 32 + 2 * j], b = Er4[q * 32 + 2 * j + 1];
            enp = fmaf(a.x, a.x, enp); enp = fmaf(a.y, a.y, enp);
            enp = fmaf(a.z, a.z, enp); enp = fmaf(a.w, a.w, enp);
            enp = fmaf(b.x, b.x, enp); enp = fmaf(b.y, b.y, enp);
            enp = fmaf(b.z, b.z, enp); enp = fmaf(b.w, b.w, enp);
            uint4 H, Lo; cvt8(a, b, H, Lo);
            const int off = r * PITCH + q * 256 + j * 16;
            *(uint4*)(sm + OFF_EH + off) = H;
            *(uint4*)(sm + OFF_EL + off) = Lo;
        }
        sEn2[t] = enp;
    }
    // ---- label argmax (first occurrence): thread t<32 owns row b0+t ----
    int y = 0;
    if (t < 32) {
        const float4* Lr4 = (const float4*)(Lb + (size_t)(b0 + t) * NR);
        float lv = -3.4e38f;
        #pragma unroll
        for (int k = 0; k < 16; ++k) {
            float4 v = Lr4[k];
            if (v.x > lv) { lv = v.x; y = 4 * k; }
            if (v.y > lv) { lv = v.y; y = 4 * k + 1; }
            if (v.z > lv) { lv = v.z; y = 4 * k + 2; }
            if (v.w > lv) { lv = v.w; y = 4 * k + 3; }
        }
    }
    __syncthreads();

    // ---- norm combines ----
    if (t < 64)      sEn[t] = sEn2[t] + sEn2[t + 64] + sEn2[t + 128] + sEn2[t + 192];
    else if (t < 96) {
        const int u = t - 64; float s = 0.f;
        #pragma unroll
        for (int k = 0; k < 8; ++k) s += sWn2[u + 32 * k];
        sWn[u] = s;
    }

    // ================= mainloop: 8 warps = 2 m-halves x 4 n-quarters =================
    const int wm = wi & 1, wn = wi >> 1;
    const u32 aoff = (u32)((wm * 16 + (L & 15)) * PITCH + ((L >> 4) << 4));
    const u32 boff = (u32)((wn * 16 + (L & 7) + ((L >> 4) << 3)) * PITCH + (((L >> 3) & 1) << 4));
    float C0[4] = {0.f, 0.f, 0.f, 0.f}, C1[4] = {0.f, 0.f, 0.f, 0.f};

    #pragma unroll
    for (int pass = 0; pass < 3; ++pass) {
        const u32 Aad = smb + (pass == 1 ? OFF_WL : OFF_WH) + aoff;
        const u32 Bad = smb + (pass == 2 ? OFF_EL : OFF_EH) + boff;
        #pragma unroll 4
        for (int kk = 0; kk < 32; ++kk) {
            u32 a0, a1, a2, a3, e0, e1, e2, e3;
            LDM4(a0, a1, a2, a3, Aad + kk * 32);
            LDM4(e0, e1, e2, e3, Bad + kk * 32);
            MMA(C0, a0, a1, a2, a3, e0, e1);
            MMA(C1, a0, a1, a2, a3, e2, e3);
        }
    }
    __syncthreads();   // all ldmatrix reads done -> safe to overwrite W region with dots

    // ---- dump dots to smem [32 b][64 r] (pitch 68) ----
    {
        const int m = wm * 16 + (L >> 2);
        const int n = wn * 16 + 2 * (L & 3);
        *(float2*)(sD + m * DPITCH + n)           = make_float2(C0[0], C0[1]);
        *(float2*)(sD + (m + 8) * DPITCH + n)     = make_float2(C0[2], C0[3]);
        *(float2*)(sD + m * DPITCH + n + 8)       = make_float2(C1[0], C1[1]);
        *(float2*)(sD + (m + 8) * DPITCH + n + 8) = make_float2(C1[2], C1[3]);
    }
    __syncthreads();

    // ================= epilogue: thread t<32 scans its own b-row =================
    if (t < 32) {
        const float wnb = sWn[t];
        const float* drow = sD + t * DPITCH;
        float v1 = -3.4e38f, v2 = -3.4e38f, plus = 0.f;
        int i1 = 0;
        #pragma unroll
        for (int r = 0; r < NR; ++r) {
            float d2 = fmaf(-2.f, drow[r], wnb + sEn[r]);
            if (r == y) plus = d2;
            if (d2 > v1) { v2 = v1; v1 = d2; i1 = r; }
            else if (d2 > v2) v2 = d2;
        }
        float minus = (i1 == y) ? v2 : v1;
        sLs[t] = 1.0f + sqrtf(fmaxf(plus, 0.f)) - sqrtf(fmaxf(minus, 0.f));
        // one-hot pred row
        float4* pr = (float4*)(pred + (size_t)(b0 + t) * NR);
        const float4 z = make_float4(0.f, 0.f, 0.f, 0.f);
        #pragma unroll
        for (int k = 0; k < 16; ++k) pr[k] = z;
        pred[(size_t)(b0 + t) * NR + i1] = 1.0f;
    }
    __syncthreads();

    // ---- per-CTA loss partial + deterministic last-CTA mean ----
    if (wi == 0) {
        float s = sLs[L];
        #pragma unroll
        for (int o = 16; o; o >>= 1) s += __shfl_xor_sync(0xffffffffu, s, o);
        if (L == 0) {
            g_part[blockIdx.x] = s;
            __threadfence();
            int old = atomicAdd(&g_ctr, 1);
            sFlag = (old == GRID - 1) ? 1 : 0;
        }
    }
    __syncthreads();
    if (sFlag && t < 32) {
        float s = 0.f;
        #pragma unroll
        for (int k = 0; k < GRID / 32; ++k) {
            float v;
            asm("ld.global.cg.f32 %0, [%1];" : "=f"(v) : "l"(g_part + t + 32 * k));
            s += v;
        }
        #pragma unroll
        for (int o = 16; o; o >>= 1) s += __shfl_xor_sync(0xffffffffu, s, o);
        if (t == 0) { *lossp = s * (1.0f / (float)NB); g_ctr = 0; }
    }
}

extern "C" void kernel_launch(void* const* d_in, const int* in_sizes, int n_in,
                              void* d_out, int out_size) {
    const float* W = nullptr; const float* E = nullptr; const float* L = nullptr;
    for (int i = 0; i < n_in; ++i) {
        if      (in_sizes[i] == NB * ND) W = (const float*)d_in[i];
        else if (in_sizes[i] == NR * ND) E = (const float*)d_in[i];
        else if (in_sizes[i] == NB * NR) L = (const float*)d_in[i];
    }
    float* out = (float*)d_out;
    cudaFuncSetAttribute(k_fused, cudaFuncAttributeMaxDynamicSharedMemorySize, SMEM_TOTAL);
    k_fused<<<GRID, NT, SMEM_TOTAL>>>(W, E, L, out, out + (out_size - 1));
}

// round 16
// speedup vs baseline: 1.5448x; 1.1235x over previous
#include <cuda_runtime.h>
#include <cstdint>

#define NB 4096
#define NR 64
#define ND 512
#define MTILE 32
#define GRID (NB / MTILE)    // 128
#define NT 256
#define PGRID 512            // prep: 512 CTAs x 8 warps = 4096 warps (one per W row)

typedef unsigned int u32;

// ---- device-global staging (bf16 hi/lo as u32-packed pairs) ----
__device__ __align__(16) u32 g_Whi[NB * ND / 2];   // 4 MB
__device__ __align__(16) u32 g_Wlo[NB * ND / 2];   // 4 MB
__device__ __align__(16) u32 g_Ehi[NR * ND / 2];   // 64 KB
__device__ __align__(16) u32 g_Elo[NR * ND / 2];   // 64 KB
__device__ float g_wn[NB];
__device__ float g_en[NR];
__device__ int   g_y[NB];
__device__ float g_part[GRID];
__device__ int   g_ctr = 0;

// ---- main-kernel smem layout (bytes); bf16 tiles, 1040B row pitch ----
#define PITCH   1040
#define OFF_WH  0
#define OFF_WL  (OFF_WH + 32 * PITCH)     // 33280
#define OFF_EH  (OFF_WL + 32 * PITCH)     // 66560
#define OFF_EL  (OFF_EH + 64 * PITCH)     // 133120
#define OFF_EN  (OFF_EL + 64 * PITCH)     // 199680 (64 f)
#define OFF_LS  (OFF_EN + 256)            // 199936 (32 f)
#define SMEM_TOTAL (OFF_LS + 128)         // 200064
#define OFF_D   OFF_WH                    // dots [32][DPITCH] f, reuses W region
#define DPITCH  68

__device__ __forceinline__ u32 smem_u32(const void* p) {
    u32 a; asm("{ .reg .u64 t; cvta.to.shared.u64 t, %1; cvt.u32.u64 %0, t; }" : "=r"(a) : "l"(p));
    return a;
}
__device__ __forceinline__ u32 pk(float lo, float hi) {   // -> bf16x2 {hi|lo}
    u32 r; asm("cvt.rn.bf16x2.f32 %0, %1, %2;" : "=r"(r) : "f"(hi), "f"(lo)); return r;
}
// float4 -> bf16 hi uint2 + residual-lo uint2
__device__ __forceinline__ void cvt4(float4 v, uint2 &H, uint2 &Lo) {
    H.x = pk(v.x, v.y); H.y = pk(v.z, v.w);
    float l0 = v.x - __uint_as_float(H.x << 16);
    float l1 = v.y - __uint_as_float(H.x & 0xffff0000u);
    float l2 = v.z - __uint_as_float(H.y << 16);
    float l3 = v.w - __uint_as_float(H.y & 0xffff0000u);
    Lo.x = pk(l0, l1); Lo.y = pk(l2, l3);
}
#define CPASYNC16(dst, src) \
    asm volatile("cp.async.cg.shared.global [%0], [%1], 16;" :: "r"(dst), "l"(src))
#define LDM4(r0, r1, r2, r3, a) \
    asm volatile("ldmatrix.sync.aligned.m8n8.x4.shared.b16 {%0,%1,%2,%3}, [%4];" \
        : "=r"(r0), "=r"(r1), "=r"(r2), "=r"(r3) : "r"(a))
#define MMA(c, a0, a1, a2, a3, b0, b1) \
    asm volatile("mma.sync.aligned.m16n8k16.row.col.f32.bf16.bf16.f32 " \
        "{%0,%1,%2,%3}, {%4,%5,%6,%7}, {%8,%9}, {%0,%1,%2,%3};" \
        : "+f"((c)[0]), "+f"((c)[1]), "+f"((c)[2]), "+f"((c)[3]) \
        : "r"(a0), "r"(a1), "r"(a2), "r"(a3), "r"(b0), "r"(b1))

// ============================================================================
// k_prep: one warp per W row — bf16 hi/lo convert + |w|^2 + label argmax.
//         Warps 0..63 (CTAs 0..7) additionally convert E row (wid_g) + |e|^2.
// ============================================================================
__global__ __launch_bounds__(NT, 8)
void k_prep(const float* __restrict__ W, const float* __restrict__ E,
            const float* __restrict__ Lb) {
    const int wid_g = blockIdx.x * 8 + (threadIdx.x >> 5);   // 0..4095
    const int L = threadIdx.x & 31;

    // ---- W row convert + norm ----
    {
        const float4* Wr = (const float4*)(W + (size_t)wid_g * ND);
        float wnp = 0.f;
        #pragma unroll
        for (int k = 0; k < 4; ++k) {
            float4 v = Wr[L + 32 * k];
            wnp = fmaf(v.x, v.x, wnp); wnp = fmaf(v.y, v.y, wnp);
            wnp = fmaf(v.z, v.z, wnp); wnp = fmaf(v.w, v.w, wnp);
            uint2 H, Lo; cvt4(v, H, Lo);
            ((uint2*)g_Whi)[(size_t)wid_g * 128 + L + 32 * k] = H;
            ((uint2*)g_Wlo)[(size_t)wid_g * 128 + L + 32 * k] = Lo;
        }
        #pragma unroll
        for (int o = 16; o; o >>= 1) wnp += __shfl_xor_sync(0xffffffffu, wnp, o);
        if (L == 0) g_wn[wid_g] = wnp;
    }
    // ---- label argmax (value desc, index asc on ties) ----
    {
        const float* Lr = Lb + (size_t)wid_g * NR;
        float lv = Lr[L]; int li = L;
        float l2 = Lr[L + 32];
        if (l2 > lv) { lv = l2; li = L + 32; }
        #pragma unroll
        for (int o = 16; o; o >>= 1) {
            float ov = __shfl_xor_sync(0xffffffffu, lv, o);
            int   oi = __shfl_xor_sync(0xffffffffu, li, o);
            if (ov > lv || (ov == lv && oi < li)) { lv = ov; li = oi; }
        }
        if (L == 0) g_y[wid_g] = li;
    }
    // ---- E rows (warps 0..63) ----
    if (wid_g < NR) {
        const float4* Er = (const float4*)(E + (size_t)wid_g * ND);
        float enp = 0.f;
        #pragma unroll
        for (int k = 0; k < 4; ++k) {
            float4 v = Er[L + 32 * k];
            enp = fmaf(v.x, v.x, enp); enp = fmaf(v.y, v.y, enp);
            enp = fmaf(v.z, v.z, enp); enp = fmaf(v.w, v.w, enp);
            uint2 H, Lo; cvt4(v, H, Lo);
            ((uint2*)g_Ehi)[(size_t)wid_g * 128 + L + 32 * k] = H;
            ((uint2*)g_Elo)[(size_t)wid_g * 128 + L + 32 * k] = Lo;
        }
        #pragma unroll
        for (int o = 16; o; o >>= 1) enp += __shfl_xor_sync(0xffffffffu, enp, o);
        if (L == 0) g_en[wid_g] = enp;
    }
}

// ============================================================================
// k_main: cp.async staging of bf16 tiles -> HMMA split-precision GEMM -> top-2
// ============================================================================
__global__ __launch_bounds__(NT, 1)
void k_main(float* __restrict__ pred, float* __restrict__ lossp) {
    extern __shared__ char sm[];
    const u32 smb = smem_u32(sm);
    float* sEn = (float*)(sm + OFF_EN);
    float* sLs = (float*)(sm + OFF_LS);
    float* sD  = (float*)(sm + OFF_D);
    __shared__ int sFlag;

    const int t  = threadIdx.x;
    const int L  = t & 31;
    const int wi = t >> 5;
    const int b0 = blockIdx.x * MTILE;

    // ---- stage all 4 tiles via cp.async (16B chunks into pitched layout) ----
    {
        const char* srcWH = (const char*)g_Whi + (size_t)b0 * 1024;
        const char* srcWL = (const char*)g_Wlo + (size_t)b0 * 1024;
        #pragma unroll
        for (int i = t; i < 2048; i += NT) {      // 32 rows x 64 chunks
            const int row = i >> 6, c = i & 63;
            const u32 d = smb + row * PITCH + c * 16;
            CPASYNC16(d + OFF_WH, srcWH + row * 1024 + c * 16);
            CPASYNC16(d + OFF_WL, srcWL + row * 1024 + c * 16);
        }
        #pragma unroll
        for (int i = t; i < 4096; i += NT) {      // 64 rows x 64 chunks
            const int row = i >> 6, c = i & 63;
            const u32 d = smb + row * PITCH + c * 16;
            CPASYNC16(d + OFF_EH, (const char*)g_Ehi + row * 1024 + c * 16);
            CPASYNC16(d + OFF_EL, (const char*)g_Elo + row * 1024 + c * 16);
        }
        asm volatile("cp.async.commit_group;" ::: "memory");
    }
    if (t < 64) sEn[t] = g_en[t];
    asm volatile("cp.async.wait_group 0;" ::: "memory");
    __syncthreads();

    // ================= mainloop: 8 warps = 2 m-halves x 4 n-quarters =================
    const int wm = wi & 1, wn = wi >> 1;
    const u32 aoff = (u32)((wm * 16 + (L & 15)) * PITCH + ((L >> 4) << 4));
    const u32 boff = (u32)((wn * 16 + (L & 7) + ((L >> 4) << 3)) * PITCH + (((L >> 3) & 1) << 4));
    float C0[4] = {0.f, 0.f, 0.f, 0.f}, C1[4] = {0.f, 0.f, 0.f, 0.f};

    #pragma unroll
    for (int pass = 0; pass < 3; ++pass) {
        const u32 Aad = smb + (pass == 1 ? OFF_WL : OFF_WH) + aoff;
        const u32 Bad = smb + (pass == 2 ? OFF_EL : OFF_EH) + boff;
        #pragma unroll 4
        for (int kk = 0; kk < 32; ++kk) {
            u32 a0, a1, a2, a3, e0, e1, e2, e3;
            LDM4(a0, a1, a2, a3, Aad + kk * 32);
            LDM4(e0, e1, e2, e3, Bad + kk * 32);
            MMA(C0, a0, a1, a2, a3, e0, e1);
            MMA(C1, a0, a1, a2, a3, e2, e3);
        }
    }
    __syncthreads();   // ldmatrix reads done -> safe to overwrite W region with dots

    // ---- dump dots to smem [32 b][64 r] ----
    {
        const int m = wm * 16 + (L >> 2);
        const int n = wn * 16 + 2 * (L & 3);
        *(float2*)(sD + m * DPITCH + n)           = make_float2(C0[0], C0[1]);
        *(float2*)(sD + (m + 8) * DPITCH + n)     = make_float2(C0[2], C0[3]);
        *(float2*)(sD + m * DPITCH + n + 8)       = make_float2(C1[0], C1[1]);
        *(float2*)(sD + (m + 8) * DPITCH + n + 8) = make_float2(C1[2], C1[3]);
    }
    __syncthreads();

    // ================= epilogue: thread t<32 scans its own b-row =================
    if (t < 32) {
        const float wnb = g_wn[b0 + t];
        const int   y   = g_y[b0 + t];
        const float* drow = sD + t * DPITCH;
        float v1 = -3.4e38f, v2 = -3.4e38f, plus = 0.f;
        int i1 = 0;
        #pragma unroll
        for (int r = 0; r < NR; ++r) {
            float d2 = fmaf(-2.f, drow[r], wnb + sEn[r]);
            if (r == y) plus = d2;
            if (d2 > v1) { v2 = v1; v1 = d2; i1 = r; }
            else if (d2 > v2) v2 = d2;
        }
        float minus = (i1 == y) ? v2 : v1;
        sLs[t] = 1.0f + sqrtf(fmaxf(plus, 0.f)) - sqrtf(fmaxf(minus, 0.f));
        // one-hot pred row
        float4* pr = (float4*)(pred + (size_t)(b0 + t) * NR);
        const float4 z = make_float4(0.f, 0.f, 0.f, 0.f);
        #pragma unroll
        for (int k = 0; k < 16; ++k) pr[k] = z;
        pred[(size_t)(b0 + t) * NR + i1] = 1.0f;
    }
    __syncthreads();

    // ---- per-CTA loss partial + deterministic last-CTA mean ----
    if (wi == 0) {
        float s = sLs[L];
        #pragma unroll
        for (int o = 16; o; o >>= 1) s += __shfl_xor_sync(0xffffffffu, s, o);
        if (L == 0) {
            g_part[blockIdx.x] = s;
            __threadfence();
            int old = atomicAdd(&g_ctr, 1);
            sFlag = (old == GRID - 1) ? 1 : 0;
        }
    }
    __syncthreads();
    if (sFlag && t < 32) {
        float s = 0.f;
        #pragma unroll
        for (int k = 0; k < GRID / 32; ++k) {
            float v;
            asm("ld.global.cg.f32 %0, [%1];" : "=f"(v) : "l"(g_part + t + 32 * k));
            s += v;
        }
        #pragma unroll
        for (int o = 16; o; o >>= 1) s += __shfl_xor_sync(0xffffffffu, s, o);
        if (t == 0) { *lossp = s * (1.0f / (float)NB); g_ctr = 0; }
    }
}

extern "C" void kernel_launch(void* const* d_in, const int* in_sizes, int n_in,
                              void* d_out, int out_size) {
    const float* W = nullptr; const float* E = nullptr; const float* L = nullptr;
    for (int i = 0; i < n_in; ++i) {
        if      (in_sizes[i] == NB * ND) W = (const float*)d_in[i];
        else if (in_sizes[i] == NR * ND) E = (const float*)d_in[i];
        else if (in_sizes[i] == NB * NR) L = (const float*)d_in[i];
    }
    float* out = (float*)d_out;
    cudaFuncSetAttribute(k_main, cudaFuncAttributeMaxDynamicSharedMemorySize, SMEM_TOTAL);
    k_prep<<<PGRID, NT>>>(W, E, L);
    k_main<<<GRID, NT, SMEM_TOTAL>>>(out, out + (out_size - 1));
}